// round 14
// baseline (speedup 1.0000x reference)
#include <cuda_runtime.h>
#include <cuda_bf16.h>
#include <cuda_fp16.h>
#include <cstdint>

#define BSZ  256
#define NTOK 196
#define DIM  384
#define NH   8
#define KD   32
#define VD   128
#define HPER 192
#define HID  1536
#define NPAIR 38416
#define MROWS (BSZ*NTOK)   // 50176
#define NBH   (BSZ*NH)     // 2048

// ---------------- scratch (static device globals; zero-initialized) -----------
__device__ float  g_qkv [(size_t)MROWS * HID];
__device__ float  g_bias[(size_t)NH * NPAIR];
__device__ __half g_xh  [(size_t)MROWS * DIM];
__device__ __half g_xl  [(size_t)MROWS * DIM];
__device__ __half g_wqh [(size_t)HID * DIM];
__device__ __half g_wph [(size_t)DIM * NH * VD];
__device__ __half g_aoh [(size_t)MROWS * NH * VD];
__device__ __half g_aol [(size_t)MROWS * NH * VD];
// fp16 attention operands (pads stay zero: never written)
__device__ __half g_q   [(size_t)NBH * 224 * 32];
__device__ __half g_kk  [(size_t)NBH * 256 * 32];
__device__ __half g_vth [(size_t)NBH * 128 * 256];   // V^T hi
__device__ __half g_vtl [(size_t)NBH * 128 * 256];   // V^T lo

// ---------------- PTX helpers -------------------------------------------------
__device__ __forceinline__ uint32_t smem_u32(const void* p) {
    uint32_t a;
    asm("{ .reg .u64 t; cvta.to.shared.u64 t, %1; cvt.u32.u64 %0, t; }"
        : "=r"(a) : "l"(p));
    return a;
}
__device__ __forceinline__ void ldsm_x4(uint32_t* r, uint32_t addr) {
    asm volatile("ldmatrix.sync.aligned.m8n8.x4.shared.b16 {%0,%1,%2,%3}, [%4];"
        : "=r"(r[0]), "=r"(r[1]), "=r"(r[2]), "=r"(r[3]) : "r"(addr));
}
__device__ __forceinline__ void mma_f16(float* c, const uint32_t* a, const uint32_t* b) {
    asm volatile(
        "mma.sync.aligned.m16n8k16.row.col.f32.f16.f16.f32 "
        "{%0,%1,%2,%3}, {%4,%5,%6,%7}, {%8,%9}, {%0,%1,%2,%3};"
        : "+f"(c[0]), "+f"(c[1]), "+f"(c[2]), "+f"(c[3])
        : "r"(a[0]), "r"(a[1]), "r"(a[2]), "r"(a[3]), "r"(b[0]), "r"(b[1]));
}

// ---------------- bias table precompute --------------------------------------
__global__ void bias_fill_kernel(const int* __restrict__ idx_raw,
                                 const float* __restrict__ ab, int n_off) {
    int i = blockIdx.x * blockDim.x + threadIdx.x;
    if (i >= NPAIR) return;
    bool is64 = (idx_raw[1] == 0);
    int idx = is64 ? idx_raw[2 * i] : idx_raw[i];
#pragma unroll
    for (int h = 0; h < NH; h++)
        g_bias[(size_t)h * NPAIR + i] = ab[h * n_off + idx];
}

// ---------------- fp32 -> fp16 hi/lo split ------------------------------------
__global__ void split_kernel(const float* __restrict__ src,
                             __half* __restrict__ hi,
                             __half* __restrict__ lo, int n4) {
    int i = blockIdx.x * blockDim.x + threadIdx.x;
    if (i >= n4) return;
    float4 v = ((const float4*)src)[i];
    __half2 hA = __floats2half2_rn(v.x, v.y);
    __half2 hB = __floats2half2_rn(v.z, v.w);
    __half2 lA = __floats2half2_rn(v.x - __low2float(hA), v.y - __high2float(hA));
    __half2 lB = __floats2half2_rn(v.z - __low2float(hB), v.w - __high2float(hB));
    ((__half2*)hi)[2 * i] = hA; ((__half2*)hi)[2 * i + 1] = hB;
    ((__half2*)lo)[2 * i] = lA; ((__half2*)lo)[2 * i + 1] = lB;
}
__global__ void split_hi_kernel(const float* __restrict__ src,
                                __half* __restrict__ hi, int n4) {
    int i = blockIdx.x * blockDim.x + threadIdx.x;
    if (i >= n4) return;
    float4 v = ((const float4*)src)[i];
    ((__half2*)hi)[2 * i]     = __floats2half2_rn(v.x, v.y);
    ((__half2*)hi)[2 * i + 1] = __floats2half2_rn(v.z, v.w);
}

// ---------------- fp16 2-pass split GEMM, 2 CTAs/SM, slim fragment liveness ---
// C = A @ B^T + bias, fp32 out, via AhBh + AlBh.
// A-fragments loaded just-in-time per mi-group: live set ~98 regs < 128 cap,
// so the (256,2) occupancy comes without spills.
#define TPAD 40
#define TILE_B (128 * TPAD * 2)     // 10240 B
#define T_AH 0
#define T_AL (TILE_B)
#define T_BH (2 * TILE_B)
#define GEMM_SMEM (3 * TILE_B)      // 30720 B

__global__ __launch_bounds__(256, 2) void gemm_mma_kernel(
    const __half* __restrict__ Ah, const __half* __restrict__ Al,
    const __half* __restrict__ Bh,
    const float* __restrict__ bias, float* __restrict__ C,
    int Ndim, int Kdim, int nchunk)
{
    extern __shared__ char smem[];
    const uint32_t sb = smem_u32(smem);
    const int tid = threadIdx.x;
    const int wid = tid >> 5, lane = tid & 31;
    const int wm = wid & 1, wn = wid >> 1;
    const int bm = blockIdx.y, bn = blockIdx.x;

    const size_t aoff = (size_t)bm * 128 * Kdim;
    const size_t boff = (size_t)bn * 128 * Kdim;
    const __half* srcs[3] = {Ah + aoff, Al + aoff, Bh + boff};
    const int toffs[3] = {T_AH, T_AL, T_BH};

    float acc[4][4][4];
#pragma unroll
    for (int i = 0; i < 4; i++)
#pragma unroll
        for (int j = 0; j < 4; j++)
#pragma unroll
            for (int r = 0; r < 4; r++) acc[i][j][r] = 0.0f;

    const int a_row = (lane & 7) + ((lane >> 3) & 1) * 8;
    const int a_kof = ((lane >> 4) & 1) * 8;
    const int b_mat = lane >> 3;
    const int b_row = ((b_mat >> 1) * 8) + (lane & 7);
    const int b_kof = (b_mat & 1) * 8;

    for (int c = 0; c < nchunk; c++) {
        const int k0 = c * 32;
        if (c > 0) __syncthreads();
#pragma unroll
        for (int t = 0; t < 3; t++) {
            const __half* s = srcs[t];
#pragma unroll
            for (int u = tid; u < 512; u += 256) {
                int row = u >> 2, seg = u & 3;
                uint4 v = *(const uint4*)(s + (size_t)row * Kdim + k0 + seg * 8);
                *(uint4*)(smem + toffs[t] + row * (TPAD * 2) + seg * 16) = v;
            }
        }
        __syncthreads();

#pragma unroll
        for (int ks = 0; ks < 2; ks++) {
            const int kk = ks * 16;
            uint32_t bh[2][4];
#pragma unroll
            for (int p = 0; p < 2; p++) {
                int nrow = wn * 32 + p * 16 + b_row;
                uint32_t off = nrow * (TPAD * 2) + (kk + b_kof) * 2;
                ldsm_x4(bh[p], sb + T_BH + off);
            }
            // A-fragments just-in-time per mi-group: only 8 A-regs live
#pragma unroll
            for (int mi = 0; mi < 4; mi++) {
                uint32_t ah[4], al[4];
                int row = wm * 64 + mi * 16 + a_row;
                uint32_t off = row * (TPAD * 2) + (kk + a_kof) * 2;
                ldsm_x4(ah, sb + T_AH + off);
                ldsm_x4(al, sb + T_AL + off);
#pragma unroll
                for (int ni = 0; ni < 4; ni++) {
                    const uint32_t* Bh2 = &bh[ni >> 1][(ni & 1) * 2];
                    mma_f16(acc[mi][ni], ah, Bh2);
                    mma_f16(acc[mi][ni], al, Bh2);
                }
            }
        }
    }

    const int m0 = bm * 128 + wm * 64;
    const int n0 = bn * 128 + wn * 32;
    const int tr = lane >> 2, tc = (lane & 3) * 2;
#pragma unroll
    for (int mi = 0; mi < 4; mi++)
#pragma unroll
        for (int ni = 0; ni < 4; ni++) {
            int row = m0 + mi * 16 + tr;
            int col = n0 + ni * 8 + tc;
            float b0 = __ldg(bias + col), b1 = __ldg(bias + col + 1);
            float2 v0 = {acc[mi][ni][0] + b0, acc[mi][ni][1] + b1};
            float2 v1 = {acc[mi][ni][2] + b0, acc[mi][ni][3] + b1};
            *(float2*)(C + (size_t)row * Ndim + col) = v0;
            *(float2*)(C + (size_t)(row + 8) * Ndim + col) = v1;
        }
}

// ---------------- QKV fp32 -> fp16 Q/K repack ---------------------------------
__global__ void qk_repack_kernel() {
    int i = blockIdx.x * blockDim.x + threadIdx.x;
    if (i >= NBH * NTOK * 16) return;
    int g  = i & 15;
    int bn = i >> 4;
    int bh = bn / NTOK, n = bn - bh * NTOK;
    int b = bh >> 3, h = bh & 7;
    const float* src = g_qkv + (size_t)(b * NTOK + n) * HID + h * HPER + g * 4;
    float4 v = *(const float4*)src;
    __half tmp[4];
    tmp[0] = __float2half(v.x); tmp[1] = __float2half(v.y);
    tmp[2] = __float2half(v.z); tmp[3] = __float2half(v.w);
    __half* dst = (g < 8)
        ? (g_q  + ((size_t)bh * 224 + n) * 32 + g * 4)
        : (g_kk + ((size_t)bh * 256 + n) * 32 + (g - 8) * 4);
    *(uint2*)dst = *(uint2*)tmp;
}

// ---------------- V transpose + fp16 hi/lo split ------------------------------
__global__ __launch_bounds__(256) void v_repack_kernel() {
    __shared__ float tile[32 * 133];
    const int nb = blockIdx.x, bh = blockIdx.y;
    const int b = bh >> 3, h = bh & 7;
    const int tid = threadIdx.x;

    for (int e = tid; e < 32 * 128; e += 256) {
        int r = e >> 7, d = e & 127;
        int n = nb * 32 + r;
        float v = 0.0f;
        if (n < NTOK)
            v = g_qkv[(size_t)(b * NTOK + n) * HID + h * HPER + 2 * KD + d];
        tile[r * 133 + d] = v;
    }
    __syncthreads();
    for (int e = tid; e < 128 * 32; e += 256) {
        int d = e >> 5, r = e & 31;
        int n = nb * 32 + r;
        float f = tile[r * 133 + d];
        __half hv = __float2half(f);
        __half lv = __float2half(f - __half2float(hv));
        size_t o = ((size_t)bh * 128 + d) * 256 + n;
        g_vth[o] = hv;
        g_vtl[o] = lv;
    }
}

// ---------------- tensor-core flash attention (R6-proven) ---------------------
#define SQ_OFF  0
#define SK_OFF  17920
#define SVH_OFF (SK_OFF + 20480)
#define SVL_OFF (SVH_OFF + 67584)
#define ATT_SMEM (SVL_OFF + 67584)

__global__ __launch_bounds__(224, 1) void attn_tc_kernel() {
    extern __shared__ char sm[];
    const uint32_t sb = smem_u32(sm);
    const int tid = threadIdx.x, w = tid >> 5, lane = tid & 31;
    const int h = blockIdx.x, b = blockIdx.y, bh = b * NH + h;

    {
        const uint4* sq = (const uint4*)(g_q  + (size_t)bh * 224 * 32);
        for (int i = tid; i < 896; i += 224) {
            int r = i >> 2, c = i & 3;
            *(uint4*)(sm + SQ_OFF + r * 80 + c * 16) = sq[i];
        }
        const uint4* sk = (const uint4*)(g_kk + (size_t)bh * 256 * 32);
        for (int i = tid; i < 1024; i += 224) {
            int r = i >> 2, c = i & 3;
            *(uint4*)(sm + SK_OFF + r * 80 + c * 16) = sk[i];
        }
        const uint4* vh = (const uint4*)(g_vth + (size_t)bh * 128 * 256);
        const uint4* vl = (const uint4*)(g_vtl + (size_t)bh * 128 * 256);
        for (int i = tid; i < 4096; i += 224) {
            int r = i >> 5, c = i & 31;
            *(uint4*)(sm + SVH_OFF + r * 528 + c * 16) = vh[i];
            *(uint4*)(sm + SVL_OFF + r * 528 + c * 16) = vl[i];
        }
    }
    __syncthreads();

    const int a_row = (lane & 7) + ((lane >> 3) & 1) * 8;
    const int a_kof = ((lane >> 4) & 1) * 8;
    const int b_mat = lane >> 3;
    const int b_row = ((b_mat >> 1) * 8) + (lane & 7);
    const int b_kof = (b_mat & 1) * 8;

    uint32_t qf[2][2][4];
#pragma unroll
    for (int mt = 0; mt < 2; mt++)
#pragma unroll
        for (int kt = 0; kt < 2; kt++)
            ldsm_x4(qf[mt][kt],
                    sb + SQ_OFF + (w * 32 + mt * 16 + a_row) * 80 + (kt * 16 + a_kof) * 2);

    float o[2][16][4];
#pragma unroll
    for (int mt = 0; mt < 2; mt++)
#pragma unroll
        for (int di = 0; di < 16; di++)
#pragma unroll
            for (int j = 0; j < 4; j++) o[mt][di][j] = 0.0f;

    float mcur[2][2] = {{-1e30f, -1e30f}, {-1e30f, -1e30f}};
    float lsum[2][2] = {{0.0f, 0.0f}, {0.0f, 0.0f}};

    const float scale = 0.1767766952966369f;
    const int qr = lane >> 2, qc = (lane & 3) * 2;

    for (int kb = 0; kb < 4; kb++) {
        float s[2][8][4];
#pragma unroll
        for (int mt = 0; mt < 2; mt++)
#pragma unroll
            for (int ni = 0; ni < 8; ni++)
#pragma unroll
                for (int j = 0; j < 4; j++) s[mt][ni][j] = 0.0f;

#pragma unroll
        for (int kt = 0; kt < 2; kt++) {
            uint32_t kf[4][4];
#pragma unroll
            for (int p = 0; p < 4; p++)
                ldsm_x4(kf[p], sb + SK_OFF + (kb * 64 + p * 16 + b_row) * 80
                               + (kt * 16 + b_kof) * 2);
#pragma unroll
            for (int mt = 0; mt < 2; mt++)
#pragma unroll
                for (int ni = 0; ni < 8; ni++)
                    mma_f16(s[mt][ni], qf[mt][kt], &kf[ni >> 1][(ni & 1) * 2]);
        }

#pragma unroll
        for (int mt = 0; mt < 2; mt++)
#pragma unroll
            for (int hf = 0; hf < 2; hf++) {
                int row = w * 32 + mt * 16 + qr + hf * 8;
                int rowc = min(row, NTOK - 1);
                const float* bb = g_bias + (size_t)h * NPAIR + rowc * NTOK;
                int j0 = hf * 2;
#pragma unroll
                for (int ni = 0; ni < 8; ni++) {
                    int key = kb * 64 + ni * 8 + qc;
                    if (key < NTOK) {
                        float2 bv = *(const float2*)(bb + key);
                        s[mt][ni][j0]     = fmaf(s[mt][ni][j0],     scale, bv.x);
                        s[mt][ni][j0 + 1] = fmaf(s[mt][ni][j0 + 1], scale, bv.y);
                    } else {
                        s[mt][ni][j0] = -1e30f;
                        s[mt][ni][j0 + 1] = -1e30f;
                    }
                }
            }

        float alpha[2][2], mnew[2][2];
#pragma unroll
        for (int mt = 0; mt < 2; mt++)
#pragma unroll
            for (int hf = 0; hf < 2; hf++) {
                int j0 = hf * 2;
                float bm = -1e30f;
#pragma unroll
                for (int ni = 0; ni < 8; ni++)
                    bm = fmaxf(bm, fmaxf(s[mt][ni][j0], s[mt][ni][j0 + 1]));
                bm = fmaxf(bm, __shfl_xor_sync(0xffffffffu, bm, 1));
                bm = fmaxf(bm, __shfl_xor_sync(0xffffffffu, bm, 2));
                float mn = fmaxf(mcur[mt][hf], bm);
                alpha[mt][hf] = __expf(mcur[mt][hf] - mn);
                mnew[mt][hf] = mn;
                mcur[mt][hf] = mn;
            }
#pragma unroll
        for (int mt = 0; mt < 2; mt++)
#pragma unroll
            for (int hf = 0; hf < 2; hf++) {
                int j0 = hf * 2;
                float ps = 0.0f;
#pragma unroll
                for (int ni = 0; ni < 8; ni++) {
                    float p0 = __expf(s[mt][ni][j0]     - mnew[mt][hf]);
                    float p1 = __expf(s[mt][ni][j0 + 1] - mnew[mt][hf]);
                    s[mt][ni][j0] = p0; s[mt][ni][j0 + 1] = p1;
                    ps += p0 + p1;
                }
                ps += __shfl_xor_sync(0xffffffffu, ps, 1);
                ps += __shfl_xor_sync(0xffffffffu, ps, 2);
                lsum[mt][hf] = lsum[mt][hf] * alpha[mt][hf] + ps;
                float a = alpha[mt][hf];
#pragma unroll
                for (int di = 0; di < 16; di++) {
                    o[mt][di][j0] *= a;
                    o[mt][di][j0 + 1] *= a;
                }
            }

        uint32_t ph[2][4][4], pl[2][4][4];
#pragma unroll
        for (int mt = 0; mt < 2; mt++)
#pragma unroll
            for (int ks = 0; ks < 4; ks++)
#pragma unroll
                for (int rr = 0; rr < 4; rr++) {
                    int ni = 2 * ks + (rr >> 1);
                    int j  = (rr & 1) * 2;
                    float x = s[mt][ni][j], y = s[mt][ni][j + 1];
                    __half2 hh = __floats2half2_rn(x, y);
                    float rx = x - __low2float(hh), ry = y - __high2float(hh);
                    __half2 hl = __floats2half2_rn(rx, ry);
                    ph[mt][ks][rr] = *reinterpret_cast<uint32_t*>(&hh);
                    pl[mt][ks][rr] = *reinterpret_cast<uint32_t*>(&hl);
                }

#pragma unroll
        for (int ks = 0; ks < 4; ks++)
#pragma unroll
            for (int dp = 0; dp < 8; dp++) {
                uint32_t v4[4];
                ldsm_x4(v4, sb + SVH_OFF + (dp * 16 + b_row) * 528
                            + (kb * 64 + ks * 16 + b_kof) * 2);
#pragma unroll
                for (int mt = 0; mt < 2; mt++) {
                    mma_f16(o[mt][2 * dp],     ph[mt][ks], &v4[0]);
                    mma_f16(o[mt][2 * dp + 1], ph[mt][ks], &v4[2]);
                    mma_f16(o[mt][2 * dp],     pl[mt][ks], &v4[0]);
                    mma_f16(o[mt][2 * dp + 1], pl[mt][ks], &v4[2]);
                }
                ldsm_x4(v4, sb + SVL_OFF + (dp * 16 + b_row) * 528
                            + (kb * 64 + ks * 16 + b_kof) * 2);
#pragma unroll
                for (int mt = 0; mt < 2; mt++) {
                    mma_f16(o[mt][2 * dp],     ph[mt][ks], &v4[0]);
                    mma_f16(o[mt][2 * dp + 1], ph[mt][ks], &v4[2]);
                }
            }
    }

#pragma unroll
    for (int mt = 0; mt < 2; mt++)
#pragma unroll
        for (int hf = 0; hf < 2; hf++) {
            int row = w * 32 + mt * 16 + qr + hf * 8;
            if (row >= NTOK) continue;
            float inv = 1.0f / lsum[mt][hf];
            int j0 = hf * 2;
            size_t base = (size_t)(b * NTOK + row) * (NH * VD) + h * VD;
#pragma unroll
            for (int di = 0; di < 16; di++) {
                int d = di * 8 + qc;
                float v0 = o[mt][di][j0] * inv;
                float v1 = o[mt][di][j0 + 1] * inv;
                __half2 hv = __floats2half2_rn(v0, v1);
                __half2 lv = __floats2half2_rn(v0 - __low2float(hv),
                                               v1 - __high2float(hv));
                *(__half2*)(g_aoh + base + d) = hv;
                *(__half2*)(g_aol + base + d) = lv;
            }
        }
}

// ---------------- launch ------------------------------------------------------
extern "C" void kernel_launch(void* const* d_in, const int* in_sizes, int n_in,
                              void* d_out, int out_size) {
    const float* x     = (const float*)d_in[0];
    const float* Wqkv  = (const float*)d_in[1];
    const float* bqkv  = (const float*)d_in[2];
    const float* Wproj = (const float*)d_in[3];
    const float* bproj = (const float*)d_in[4];
    const float* ab    = (const float*)d_in[5];
    const int*   idxs  = (const int*)  d_in[6];
    float* out = (float*)d_out;

    int n_off = in_sizes[5] / NH;

    void *p_qkv, *p_xh, *p_xl, *p_wqh, *p_wph, *p_aoh, *p_aol;
    cudaGetSymbolAddress(&p_qkv, g_qkv);
    cudaGetSymbolAddress(&p_xh, g_xh);   cudaGetSymbolAddress(&p_xl, g_xl);
    cudaGetSymbolAddress(&p_wqh, g_wqh);
    cudaGetSymbolAddress(&p_wph, g_wph);
    cudaGetSymbolAddress(&p_aoh, g_aoh); cudaGetSymbolAddress(&p_aol, g_aol);

    cudaFuncSetAttribute(gemm_mma_kernel,
                         cudaFuncAttributeMaxDynamicSharedMemorySize, GEMM_SMEM);
    cudaFuncSetAttribute(attn_tc_kernel,
                         cudaFuncAttributeMaxDynamicSharedMemorySize, ATT_SMEM);

    bias_fill_kernel<<<(NPAIR + 255) / 256, 256>>>(idxs, ab, n_off);
    {
        int n4 = MROWS * DIM / 4;
        split_kernel<<<(n4 + 255) / 256, 256>>>(x, (__half*)p_xh, (__half*)p_xl, n4);
    }
    {
        int n4 = HID * DIM / 4;
        split_hi_kernel<<<(n4 + 255) / 256, 256>>>(Wqkv, (__half*)p_wqh, n4);
    }
    {
        int n4 = DIM * NH * VD / 4;
        split_hi_kernel<<<(n4 + 255) / 256, 256>>>(Wproj, (__half*)p_wph, n4);
    }

    // QKV gemm -> g_qkv (fp32)
    gemm_mma_kernel<<<dim3(HID / 128, MROWS / 128), 256, GEMM_SMEM>>>(
        (const __half*)p_xh, (const __half*)p_xl, (const __half*)p_wqh,
        bqkv, (float*)p_qkv, HID, DIM, DIM / 32);

    // repack to fp16 attention operands
    {
        int tot = NBH * NTOK * 16;
        qk_repack_kernel<<<(tot + 255) / 256, 256>>>();
    }
    v_repack_kernel<<<dim3(7, NBH), 256>>>();

    // tensor-core flash attention -> g_aoh/g_aol
    attn_tc_kernel<<<dim3(NH, BSZ), 224, ATT_SMEM>>>();

    // proj gemm -> out
    gemm_mma_kernel<<<dim3(DIM / 128, MROWS / 128), 256, GEMM_SMEM>>>(
        (const __half*)p_aoh, (const __half*)p_aol, (const __half*)p_wph,
        bproj, out, DIM, NH * VD, (NH * VD) / 32);
}

// round 15
// speedup vs baseline: 1.2071x; 1.2071x over previous
#include <cuda_runtime.h>
#include <cuda_bf16.h>
#include <cuda_fp16.h>
#include <cstdint>

#define BSZ  256
#define NTOK 196
#define DIM  384
#define NH   8
#define KD   32
#define VD   128
#define HPER 192
#define HID  1536
#define NPAIR 38416
#define MROWS (BSZ*NTOK)   // 50176
#define NBH   (BSZ*NH)     // 2048

// ---------------- scratch (static device globals; zero-initialized) -----------
__device__ float  g_qkv [(size_t)MROWS * HID];
__device__ float  g_bias[(size_t)NH * NPAIR];
__device__ __half g_xh  [(size_t)MROWS * DIM];
__device__ __half g_wqh [(size_t)HID * DIM];
__device__ __half g_wph [(size_t)DIM * NH * VD];
__device__ __half g_aoh [(size_t)MROWS * NH * VD];
// fp16 attention operands (pads stay zero: never written)
__device__ __half g_q   [(size_t)NBH * 224 * 32];
__device__ __half g_kk  [(size_t)NBH * 256 * 32];
__device__ __half g_vth [(size_t)NBH * 128 * 256];   // V^T hi
__device__ __half g_vtl [(size_t)NBH * 128 * 256];   // V^T lo

// ---------------- PTX helpers -------------------------------------------------
__device__ __forceinline__ uint32_t smem_u32(const void* p) {
    uint32_t a;
    asm("{ .reg .u64 t; cvta.to.shared.u64 t, %1; cvt.u32.u64 %0, t; }"
        : "=r"(a) : "l"(p));
    return a;
}
__device__ __forceinline__ void ldsm_x4(uint32_t* r, uint32_t addr) {
    asm volatile("ldmatrix.sync.aligned.m8n8.x4.shared.b16 {%0,%1,%2,%3}, [%4];"
        : "=r"(r[0]), "=r"(r[1]), "=r"(r[2]), "=r"(r[3]) : "r"(addr));
}
__device__ __forceinline__ void mma_f16(float* c, const uint32_t* a, const uint32_t* b) {
    asm volatile(
        "mma.sync.aligned.m16n8k16.row.col.f32.f16.f16.f32 "
        "{%0,%1,%2,%3}, {%4,%5,%6,%7}, {%8,%9}, {%0,%1,%2,%3};"
        : "+f"(c[0]), "+f"(c[1]), "+f"(c[2]), "+f"(c[3])
        : "r"(a[0]), "r"(a[1]), "r"(a[2]), "r"(a[3]), "r"(b[0]), "r"(b[1]));
}

// ---------------- bias table precompute --------------------------------------
__global__ void bias_fill_kernel(const int* __restrict__ idx_raw,
                                 const float* __restrict__ ab, int n_off) {
    int i = blockIdx.x * blockDim.x + threadIdx.x;
    if (i >= NPAIR) return;
    bool is64 = (idx_raw[1] == 0);
    int idx = is64 ? idx_raw[2 * i] : idx_raw[i];
#pragma unroll
    for (int h = 0; h < NH; h++)
        g_bias[(size_t)h * NPAIR + i] = ab[h * n_off + idx];
}

// ---------------- fp32 -> fp16 convert (hi only) -------------------------------
__global__ void split_hi_kernel(const float* __restrict__ src,
                                __half* __restrict__ hi, int n4) {
    int i = blockIdx.x * blockDim.x + threadIdx.x;
    if (i >= n4) return;
    float4 v = ((const float4*)src)[i];
    ((__half2*)hi)[2 * i]     = __floats2half2_rn(v.x, v.y);
    ((__half2*)hi)[2 * i + 1] = __floats2half2_rn(v.z, v.w);
}

// ---------------- fp16 1-pass GEMM, 2 CTAs/SM (R13 shell) ---------------------
// C = Ah @ Bh^T + bias, fp32 accum. Error ~3e-4 rel (A_lo*B + A*B_lo dropped),
// inside the 1e-3 gate with 3x margin.
#define TPAD 40
#define TILE_B (128 * TPAD * 2)     // 10240 B
#define T_AH 0
#define T_BH (TILE_B)
#define GEMM_SMEM (2 * TILE_B)      // 20480 B

__global__ __launch_bounds__(256, 2) void gemm_mma_kernel(
    const __half* __restrict__ Ah, const __half* __restrict__ Bh,
    const float* __restrict__ bias, float* __restrict__ C,
    int Ndim, int Kdim, int nchunk)
{
    extern __shared__ char smem[];
    const uint32_t sb = smem_u32(smem);
    const int tid = threadIdx.x;
    const int wid = tid >> 5, lane = tid & 31;
    const int wm = wid & 1, wn = wid >> 1;
    const int bm = blockIdx.y, bn = blockIdx.x;

    const __half* srcs[2] = {Ah + (size_t)bm * 128 * Kdim,
                             Bh + (size_t)bn * 128 * Kdim};
    const int toffs[2] = {T_AH, T_BH};

    float acc[4][4][4];
#pragma unroll
    for (int i = 0; i < 4; i++)
#pragma unroll
        for (int j = 0; j < 4; j++)
#pragma unroll
            for (int r = 0; r < 4; r++) acc[i][j][r] = 0.0f;

    const int a_row = (lane & 7) + ((lane >> 3) & 1) * 8;
    const int a_kof = ((lane >> 4) & 1) * 8;
    const int b_mat = lane >> 3;
    const int b_row = ((b_mat >> 1) * 8) + (lane & 7);
    const int b_kof = (b_mat & 1) * 8;

    for (int c = 0; c < nchunk; c++) {
        const int k0 = c * 32;
        if (c > 0) __syncthreads();
#pragma unroll
        for (int t = 0; t < 2; t++) {
            const __half* s = srcs[t];
#pragma unroll
            for (int u = tid; u < 512; u += 256) {
                int row = u >> 2, seg = u & 3;
                uint4 v = *(const uint4*)(s + (size_t)row * Kdim + k0 + seg * 8);
                *(uint4*)(smem + toffs[t] + row * (TPAD * 2) + seg * 16) = v;
            }
        }
        __syncthreads();

#pragma unroll
        for (int ks = 0; ks < 2; ks++) {
            const int kk = ks * 16;
            uint32_t ah[4][4], bh[2][4];
#pragma unroll
            for (int mi = 0; mi < 4; mi++) {
                int row = wm * 64 + mi * 16 + a_row;
                ldsm_x4(ah[mi], sb + T_AH + row * (TPAD * 2) + (kk + a_kof) * 2);
            }
#pragma unroll
            for (int p = 0; p < 2; p++) {
                int nrow = wn * 32 + p * 16 + b_row;
                ldsm_x4(bh[p], sb + T_BH + nrow * (TPAD * 2) + (kk + b_kof) * 2);
            }
#pragma unroll
            for (int mi = 0; mi < 4; mi++)
#pragma unroll
                for (int ni = 0; ni < 4; ni++)
                    mma_f16(acc[mi][ni], ah[mi], &bh[ni >> 1][(ni & 1) * 2]);
        }
    }

    const int m0 = bm * 128 + wm * 64;
    const int n0 = bn * 128 + wn * 32;
    const int tr = lane >> 2, tc = (lane & 3) * 2;
#pragma unroll
    for (int mi = 0; mi < 4; mi++)
#pragma unroll
        for (int ni = 0; ni < 4; ni++) {
            int row = m0 + mi * 16 + tr;
            int col = n0 + ni * 8 + tc;
            float b0 = __ldg(bias + col), b1 = __ldg(bias + col + 1);
            float2 v0 = {acc[mi][ni][0] + b0, acc[mi][ni][1] + b1};
            float2 v1 = {acc[mi][ni][2] + b0, acc[mi][ni][3] + b1};
            *(float2*)(C + (size_t)row * Ndim + col) = v0;
            *(float2*)(C + (size_t)(row + 8) * Ndim + col) = v1;
        }
}

// ---------------- QKV fp32 -> fp16 Q/K repack ---------------------------------
__global__ void qk_repack_kernel() {
    int i = blockIdx.x * blockDim.x + threadIdx.x;
    if (i >= NBH * NTOK * 16) return;
    int g  = i & 15;
    int bn = i >> 4;
    int bh = bn / NTOK, n = bn - bh * NTOK;
    int b = bh >> 3, h = bh & 7;
    const float* src = g_qkv + (size_t)(b * NTOK + n) * HID + h * HPER + g * 4;
    float4 v = *(const float4*)src;
    __half tmp[4];
    tmp[0] = __float2half(v.x); tmp[1] = __float2half(v.y);
    tmp[2] = __float2half(v.z); tmp[3] = __float2half(v.w);
    __half* dst = (g < 8)
        ? (g_q  + ((size_t)bh * 224 + n) * 32 + g * 4)
        : (g_kk + ((size_t)bh * 256 + n) * 32 + (g - 8) * 4);
    *(uint2*)dst = *(uint2*)tmp;
}

// ---------------- V transpose + fp16 hi/lo split ------------------------------
__global__ __launch_bounds__(256) void v_repack_kernel() {
    __shared__ float tile[32 * 133];
    const int nb = blockIdx.x, bh = blockIdx.y;
    const int b = bh >> 3, h = bh & 7;
    const int tid = threadIdx.x;

    for (int e = tid; e < 32 * 128; e += 256) {
        int r = e >> 7, d = e & 127;
        int n = nb * 32 + r;
        float v = 0.0f;
        if (n < NTOK)
            v = g_qkv[(size_t)(b * NTOK + n) * HID + h * HPER + 2 * KD + d];
        tile[r * 133 + d] = v;
    }
    __syncthreads();
    for (int e = tid; e < 128 * 32; e += 256) {
        int d = e >> 5, r = e & 31;
        int n = nb * 32 + r;
        float f = tile[r * 133 + d];
        __half hv = __float2half(f);
        __half lv = __float2half(f - __half2float(hv));
        size_t o = ((size_t)bh * 128 + d) * 256 + n;
        g_vth[o] = hv;
        g_vtl[o] = lv;
    }
}

// ---------------- tensor-core flash attention (R6-proven) ---------------------
#define SQ_OFF  0
#define SK_OFF  17920
#define SVH_OFF (SK_OFF + 20480)
#define SVL_OFF (SVH_OFF + 67584)
#define ATT_SMEM (SVL_OFF + 67584)

__global__ __launch_bounds__(224, 1) void attn_tc_kernel() {
    extern __shared__ char sm[];
    const uint32_t sb = smem_u32(sm);
    const int tid = threadIdx.x, w = tid >> 5, lane = tid & 31;
    const int h = blockIdx.x, b = blockIdx.y, bh = b * NH + h;

    {
        const uint4* sq = (const uint4*)(g_q  + (size_t)bh * 224 * 32);
        for (int i = tid; i < 896; i += 224) {
            int r = i >> 2, c = i & 3;
            *(uint4*)(sm + SQ_OFF + r * 80 + c * 16) = sq[i];
        }
        const uint4* sk = (const uint4*)(g_kk + (size_t)bh * 256 * 32);
        for (int i = tid; i < 1024; i += 224) {
            int r = i >> 2, c = i & 3;
            *(uint4*)(sm + SK_OFF + r * 80 + c * 16) = sk[i];
        }
        const uint4* vh = (const uint4*)(g_vth + (size_t)bh * 128 * 256);
        const uint4* vl = (const uint4*)(g_vtl + (size_t)bh * 128 * 256);
        for (int i = tid; i < 4096; i += 224) {
            int r = i >> 5, c = i & 31;
            *(uint4*)(sm + SVH_OFF + r * 528 + c * 16) = vh[i];
            *(uint4*)(sm + SVL_OFF + r * 528 + c * 16) = vl[i];
        }
    }
    __syncthreads();

    const int a_row = (lane & 7) + ((lane >> 3) & 1) * 8;
    const int a_kof = ((lane >> 4) & 1) * 8;
    const int b_mat = lane >> 3;
    const int b_row = ((b_mat >> 1) * 8) + (lane & 7);
    const int b_kof = (b_mat & 1) * 8;

    uint32_t qf[2][2][4];
#pragma unroll
    for (int mt = 0; mt < 2; mt++)
#pragma unroll
        for (int kt = 0; kt < 2; kt++)
            ldsm_x4(qf[mt][kt],
                    sb + SQ_OFF + (w * 32 + mt * 16 + a_row) * 80 + (kt * 16 + a_kof) * 2);

    float o[2][16][4];
#pragma unroll
    for (int mt = 0; mt < 2; mt++)
#pragma unroll
        for (int di = 0; di < 16; di++)
#pragma unroll
            for (int j = 0; j < 4; j++) o[mt][di][j] = 0.0f;

    float mcur[2][2] = {{-1e30f, -1e30f}, {-1e30f, -1e30f}};
    float lsum[2][2] = {{0.0f, 0.0f}, {0.0f, 0.0f}};

    const float scale = 0.1767766952966369f;
    const int qr = lane >> 2, qc = (lane & 3) * 2;

    for (int kb = 0; kb < 4; kb++) {
        float s[2][8][4];
#pragma unroll
        for (int mt = 0; mt < 2; mt++)
#pragma unroll
            for (int ni = 0; ni < 8; ni++)
#pragma unroll
                for (int j = 0; j < 4; j++) s[mt][ni][j] = 0.0f;

#pragma unroll
        for (int kt = 0; kt < 2; kt++) {
            uint32_t kf[4][4];
#pragma unroll
            for (int p = 0; p < 4; p++)
                ldsm_x4(kf[p], sb + SK_OFF + (kb * 64 + p * 16 + b_row) * 80
                               + (kt * 16 + b_kof) * 2);
#pragma unroll
            for (int mt = 0; mt < 2; mt++)
#pragma unroll
                for (int ni = 0; ni < 8; ni++)
                    mma_f16(s[mt][ni], qf[mt][kt], &kf[ni >> 1][(ni & 1) * 2]);
        }

#pragma unroll
        for (int mt = 0; mt < 2; mt++)
#pragma unroll
            for (int hf = 0; hf < 2; hf++) {
                int row = w * 32 + mt * 16 + qr + hf * 8;
                int rowc = min(row, NTOK - 1);
                const float* bb = g_bias + (size_t)h * NPAIR + rowc * NTOK;
                int j0 = hf * 2;
#pragma unroll
                for (int ni = 0; ni < 8; ni++) {
                    int key = kb * 64 + ni * 8 + qc;
                    if (key < NTOK) {
                        float2 bv = *(const float2*)(bb + key);
                        s[mt][ni][j0]     = fmaf(s[mt][ni][j0],     scale, bv.x);
                        s[mt][ni][j0 + 1] = fmaf(s[mt][ni][j0 + 1], scale, bv.y);
                    } else {
                        s[mt][ni][j0] = -1e30f;
                        s[mt][ni][j0 + 1] = -1e30f;
                    }
                }
            }

        float alpha[2][2], mnew[2][2];
#pragma unroll
        for (int mt = 0; mt < 2; mt++)
#pragma unroll
            for (int hf = 0; hf < 2; hf++) {
                int j0 = hf * 2;
                float bm = -1e30f;
#pragma unroll
                for (int ni = 0; ni < 8; ni++)
                    bm = fmaxf(bm, fmaxf(s[mt][ni][j0], s[mt][ni][j0 + 1]));
                bm = fmaxf(bm, __shfl_xor_sync(0xffffffffu, bm, 1));
                bm = fmaxf(bm, __shfl_xor_sync(0xffffffffu, bm, 2));
                float mn = fmaxf(mcur[mt][hf], bm);
                alpha[mt][hf] = __expf(mcur[mt][hf] - mn);
                mnew[mt][hf] = mn;
                mcur[mt][hf] = mn;
            }
#pragma unroll
        for (int mt = 0; mt < 2; mt++)
#pragma unroll
            for (int hf = 0; hf < 2; hf++) {
                int j0 = hf * 2;
                float ps = 0.0f;
#pragma unroll
                for (int ni = 0; ni < 8; ni++) {
                    float p0 = __expf(s[mt][ni][j0]     - mnew[mt][hf]);
                    float p1 = __expf(s[mt][ni][j0 + 1] - mnew[mt][hf]);
                    s[mt][ni][j0] = p0; s[mt][ni][j0 + 1] = p1;
                    ps += p0 + p1;
                }
                ps += __shfl_xor_sync(0xffffffffu, ps, 1);
                ps += __shfl_xor_sync(0xffffffffu, ps, 2);
                lsum[mt][hf] = lsum[mt][hf] * alpha[mt][hf] + ps;
                float a = alpha[mt][hf];
#pragma unroll
                for (int di = 0; di < 16; di++) {
                    o[mt][di][j0] *= a;
                    o[mt][di][j0 + 1] *= a;
                }
            }

        uint32_t ph[2][4][4], pl[2][4][4];
#pragma unroll
        for (int mt = 0; mt < 2; mt++)
#pragma unroll
            for (int ks = 0; ks < 4; ks++)
#pragma unroll
                for (int rr = 0; rr < 4; rr++) {
                    int ni = 2 * ks + (rr >> 1);
                    int j  = (rr & 1) * 2;
                    float x = s[mt][ni][j], y = s[mt][ni][j + 1];
                    __half2 hh = __floats2half2_rn(x, y);
                    float rx = x - __low2float(hh), ry = y - __high2float(hh);
                    __half2 hl = __floats2half2_rn(rx, ry);
                    ph[mt][ks][rr] = *reinterpret_cast<uint32_t*>(&hh);
                    pl[mt][ks][rr] = *reinterpret_cast<uint32_t*>(&hl);
                }

#pragma unroll
        for (int ks = 0; ks < 4; ks++)
#pragma unroll
            for (int dp = 0; dp < 8; dp++) {
                uint32_t v4[4];
                ldsm_x4(v4, sb + SVH_OFF + (dp * 16 + b_row) * 528
                            + (kb * 64 + ks * 16 + b_kof) * 2);
#pragma unroll
                for (int mt = 0; mt < 2; mt++) {
                    mma_f16(o[mt][2 * dp],     ph[mt][ks], &v4[0]);
                    mma_f16(o[mt][2 * dp + 1], ph[mt][ks], &v4[2]);
                    mma_f16(o[mt][2 * dp],     pl[mt][ks], &v4[0]);
                    mma_f16(o[mt][2 * dp + 1], pl[mt][ks], &v4[2]);
                }
                ldsm_x4(v4, sb + SVL_OFF + (dp * 16 + b_row) * 528
                            + (kb * 64 + ks * 16 + b_kof) * 2);
#pragma unroll
                for (int mt = 0; mt < 2; mt++) {
                    mma_f16(o[mt][2 * dp],     ph[mt][ks], &v4[0]);
                    mma_f16(o[mt][2 * dp + 1], ph[mt][ks], &v4[2]);
                }
            }
    }

#pragma unroll
    for (int mt = 0; mt < 2; mt++)
#pragma unroll
        for (int hf = 0; hf < 2; hf++) {
            int row = w * 32 + mt * 16 + qr + hf * 8;
            if (row >= NTOK) continue;
            float inv = 1.0f / lsum[mt][hf];
            int j0 = hf * 2;
            size_t base = (size_t)(b * NTOK + row) * (NH * VD) + h * VD;
#pragma unroll
            for (int di = 0; di < 16; di++) {
                int d = di * 8 + qc;
                float v0 = o[mt][di][j0] * inv;
                float v1 = o[mt][di][j0 + 1] * inv;
                *(__half2*)(g_aoh + base + d) = __floats2half2_rn(v0, v1);
            }
        }
}

// ---------------- launch ------------------------------------------------------
extern "C" void kernel_launch(void* const* d_in, const int* in_sizes, int n_in,
                              void* d_out, int out_size) {
    const float* x     = (const float*)d_in[0];
    const float* Wqkv  = (const float*)d_in[1];
    const float* bqkv  = (const float*)d_in[2];
    const float* Wproj = (const float*)d_in[3];
    const float* bproj = (const float*)d_in[4];
    const float* ab    = (const float*)d_in[5];
    const int*   idxs  = (const int*)  d_in[6];
    float* out = (float*)d_out;

    int n_off = in_sizes[5] / NH;

    void *p_qkv, *p_xh, *p_wqh, *p_wph, *p_aoh;
    cudaGetSymbolAddress(&p_qkv, g_qkv);
    cudaGetSymbolAddress(&p_xh, g_xh);
    cudaGetSymbolAddress(&p_wqh, g_wqh);
    cudaGetSymbolAddress(&p_wph, g_wph);
    cudaGetSymbolAddress(&p_aoh, g_aoh);

    cudaFuncSetAttribute(gemm_mma_kernel,
                         cudaFuncAttributeMaxDynamicSharedMemorySize, GEMM_SMEM);
    cudaFuncSetAttribute(attn_tc_kernel,
                         cudaFuncAttributeMaxDynamicSharedMemorySize, ATT_SMEM);

    bias_fill_kernel<<<(NPAIR + 255) / 256, 256>>>(idxs, ab, n_off);
    {
        int n4 = MROWS * DIM / 4;
        split_hi_kernel<<<(n4 + 255) / 256, 256>>>(x, (__half*)p_xh, n4);
    }
    {
        int n4 = HID * DIM / 4;
        split_hi_kernel<<<(n4 + 255) / 256, 256>>>(Wqkv, (__half*)p_wqh, n4);
    }
    {
        int n4 = DIM * NH * VD / 4;
        split_hi_kernel<<<(n4 + 255) / 256, 256>>>(Wproj, (__half*)p_wph, n4);
    }

    // QKV gemm -> g_qkv (fp32)
    gemm_mma_kernel<<<dim3(HID / 128, MROWS / 128), 256, GEMM_SMEM>>>(
        (const __half*)p_xh, (const __half*)p_wqh,
        bqkv, (float*)p_qkv, HID, DIM, DIM / 32);

    // repack to fp16 attention operands
    {
        int tot = NBH * NTOK * 16;
        qk_repack_kernel<<<(tot + 255) / 256, 256>>>();
    }
    v_repack_kernel<<<dim3(7, NBH), 256>>>();

    // tensor-core flash attention -> g_aoh
    attn_tc_kernel<<<dim3(NH, BSZ), 224, ATT_SMEM>>>();

    // proj gemm -> out
    gemm_mma_kernel<<<dim3(DIM / 128, MROWS / 128), 256, GEMM_SMEM>>>(
        (const __half*)p_aoh, (const __half*)p_wph,
        bproj, out, DIM, NH * VD, (NH * VD) / 32);
}

// round 16
// speedup vs baseline: 1.3292x; 1.1012x over previous
#include <cuda_runtime.h>
#include <cuda_bf16.h>
#include <cuda_fp16.h>
#include <cstdint>

#define BSZ  256
#define NTOK 196
#define DIM  384
#define NH   8
#define KD   32
#define VD   128
#define HPER 192
#define HID  1536
#define NPAIR 38416
#define MROWS (BSZ*NTOK)   // 50176
#define NBH   (BSZ*NH)     // 2048

// ---------------- scratch (static device globals; zero-initialized) -----------
__device__ float  g_qkv [(size_t)MROWS * HID];
__device__ float  g_bias[(size_t)NH * NPAIR];
__device__ __half g_xh  [(size_t)MROWS * DIM];
__device__ __half g_wqh [(size_t)HID * DIM];
__device__ __half g_wph [(size_t)DIM * NH * VD];
__device__ __half g_aoh [(size_t)MROWS * NH * VD];
// fp16 attention operands (pads stay zero: never written)
__device__ __half g_q   [(size_t)NBH * 224 * 32];
__device__ __half g_kk  [(size_t)NBH * 256 * 32];
__device__ __half g_vth [(size_t)NBH * 128 * 256];   // V^T hi
__device__ __half g_vtl [(size_t)NBH * 128 * 256];   // V^T lo

// ---------------- PTX helpers -------------------------------------------------
__device__ __forceinline__ uint32_t smem_u32(const void* p) {
    uint32_t a;
    asm("{ .reg .u64 t; cvta.to.shared.u64 t, %1; cvt.u32.u64 %0, t; }"
        : "=r"(a) : "l"(p));
    return a;
}
__device__ __forceinline__ void ldsm_x4(uint32_t* r, uint32_t addr) {
    asm volatile("ldmatrix.sync.aligned.m8n8.x4.shared.b16 {%0,%1,%2,%3}, [%4];"
        : "=r"(r[0]), "=r"(r[1]), "=r"(r[2]), "=r"(r[3]) : "r"(addr));
}
__device__ __forceinline__ void mma_f16(float* c, const uint32_t* a, const uint32_t* b) {
    asm volatile(
        "mma.sync.aligned.m16n8k16.row.col.f32.f16.f16.f32 "
        "{%0,%1,%2,%3}, {%4,%5,%6,%7}, {%8,%9}, {%0,%1,%2,%3};"
        : "+f"(c[0]), "+f"(c[1]), "+f"(c[2]), "+f"(c[3])
        : "r"(a[0]), "r"(a[1]), "r"(a[2]), "r"(a[3]), "r"(b[0]), "r"(b[1]));
}

// ---------------- bias table precompute --------------------------------------
__global__ void bias_fill_kernel(const int* __restrict__ idx_raw,
                                 const float* __restrict__ ab, int n_off) {
    int i = blockIdx.x * blockDim.x + threadIdx.x;
    if (i >= NPAIR) return;
    bool is64 = (idx_raw[1] == 0);
    int idx = is64 ? idx_raw[2 * i] : idx_raw[i];
#pragma unroll
    for (int h = 0; h < NH; h++)
        g_bias[(size_t)h * NPAIR + i] = ab[h * n_off + idx];
}

// ---------------- fp32 -> fp16 convert (hi only) -------------------------------
__global__ void split_hi_kernel(const float* __restrict__ src,
                                __half* __restrict__ hi, int n4) {
    int i = blockIdx.x * blockDim.x + threadIdx.x;
    if (i >= n4) return;
    float4 v = ((const float4*)src)[i];
    ((__half2*)hi)[2 * i]     = __floats2half2_rn(v.x, v.y);
    ((__half2*)hi)[2 * i + 1] = __floats2half2_rn(v.z, v.w);
}

// ---------------- fp16 1-pass GEMM, K-chunk 64, 2 CTAs/SM ---------------------
// C = Ah @ Bh^T + bias, fp32 accum. Chunk 64 halves per-chunk overhead events;
// (256,2) co-residency hides the rest. Row pad 72 (144 B) -> ldsm conflict-free.
#define TPAD2 72
#define TILE_B2 (128 * TPAD2 * 2)    // 18432 B
#define T_AH 0
#define T_BH (TILE_B2)
#define GEMM_SMEM (2 * TILE_B2)      // 36864 B

__global__ __launch_bounds__(256, 2) void gemm_mma_kernel(
    const __half* __restrict__ Ah, const __half* __restrict__ Bh,
    const float* __restrict__ bias, float* __restrict__ C,
    int Ndim, int Kdim, int nchunk)
{
    extern __shared__ char smem[];
    const uint32_t sb = smem_u32(smem);
    const int tid = threadIdx.x;
    const int wid = tid >> 5, lane = tid & 31;
    const int wm = wid & 1, wn = wid >> 1;
    const int bm = blockIdx.y, bn = blockIdx.x;

    const __half* srcs[2] = {Ah + (size_t)bm * 128 * Kdim,
                             Bh + (size_t)bn * 128 * Kdim};
    const int toffs[2] = {T_AH, T_BH};

    float acc[4][4][4];
#pragma unroll
    for (int i = 0; i < 4; i++)
#pragma unroll
        for (int j = 0; j < 4; j++)
#pragma unroll
            for (int r = 0; r < 4; r++) acc[i][j][r] = 0.0f;

    const int a_row = (lane & 7) + ((lane >> 3) & 1) * 8;
    const int a_kof = ((lane >> 4) & 1) * 8;
    const int b_mat = lane >> 3;
    const int b_row = ((b_mat >> 1) * 8) + (lane & 7);
    const int b_kof = (b_mat & 1) * 8;

    for (int c = 0; c < nchunk; c++) {
        const int k0 = c * 64;
        if (c > 0) __syncthreads();
        // each tile: 128 rows x 64 fp16 = 1024 uint4; 2 tiles, 256 threads
#pragma unroll
        for (int t = 0; t < 2; t++) {
            const __half* s = srcs[t];
#pragma unroll
            for (int u = tid; u < 1024; u += 256) {
                int row = u >> 3, seg = u & 7;
                uint4 v = *(const uint4*)(s + (size_t)row * Kdim + k0 + seg * 8);
                *(uint4*)(smem + toffs[t] + row * (TPAD2 * 2) + seg * 16) = v;
            }
        }
        __syncthreads();

#pragma unroll
        for (int ks = 0; ks < 4; ks++) {
            const int kk = ks * 16;
            uint32_t ah[4][4], bh[2][4];
#pragma unroll
            for (int mi = 0; mi < 4; mi++) {
                int row = wm * 64 + mi * 16 + a_row;
                ldsm_x4(ah[mi], sb + T_AH + row * (TPAD2 * 2) + (kk + a_kof) * 2);
            }
#pragma unroll
            for (int p = 0; p < 2; p++) {
                int nrow = wn * 32 + p * 16 + b_row;
                ldsm_x4(bh[p], sb + T_BH + nrow * (TPAD2 * 2) + (kk + b_kof) * 2);
            }
#pragma unroll
            for (int mi = 0; mi < 4; mi++)
#pragma unroll
                for (int ni = 0; ni < 4; ni++)
                    mma_f16(acc[mi][ni], ah[mi], &bh[ni >> 1][(ni & 1) * 2]);
        }
    }

    const int m0 = bm * 128 + wm * 64;
    const int n0 = bn * 128 + wn * 32;
    const int tr = lane >> 2, tc = (lane & 3) * 2;
#pragma unroll
    for (int mi = 0; mi < 4; mi++)
#pragma unroll
        for (int ni = 0; ni < 4; ni++) {
            int row = m0 + mi * 16 + tr;
            int col = n0 + ni * 8 + tc;
            float b0 = __ldg(bias + col), b1 = __ldg(bias + col + 1);
            float2 v0 = {acc[mi][ni][0] + b0, acc[mi][ni][1] + b1};
            float2 v1 = {acc[mi][ni][2] + b0, acc[mi][ni][3] + b1};
            *(float2*)(C + (size_t)row * Ndim + col) = v0;
            *(float2*)(C + (size_t)(row + 8) * Ndim + col) = v1;
        }
}

// ---------------- QKV fp32 -> fp16 Q/K repack ---------------------------------
__global__ void qk_repack_kernel() {
    int i = blockIdx.x * blockDim.x + threadIdx.x;
    if (i >= NBH * NTOK * 16) return;
    int g  = i & 15;
    int bn = i >> 4;
    int bh = bn / NTOK, n = bn - bh * NTOK;
    int b = bh >> 3, h = bh & 7;
    const float* src = g_qkv + (size_t)(b * NTOK + n) * HID + h * HPER + g * 4;
    float4 v = *(const float4*)src;
    __half tmp[4];
    tmp[0] = __float2half(v.x); tmp[1] = __float2half(v.y);
    tmp[2] = __float2half(v.z); tmp[3] = __float2half(v.w);
    __half* dst = (g < 8)
        ? (g_q  + ((size_t)bh * 224 + n) * 32 + g * 4)
        : (g_kk + ((size_t)bh * 256 + n) * 32 + (g - 8) * 4);
    *(uint2*)dst = *(uint2*)tmp;
}

// ---------------- V transpose + fp16 hi/lo split ------------------------------
__global__ __launch_bounds__(256) void v_repack_kernel() {
    __shared__ float tile[32 * 133];
    const int nb = blockIdx.x, bh = blockIdx.y;
    const int b = bh >> 3, h = bh & 7;
    const int tid = threadIdx.x;

    for (int e = tid; e < 32 * 128; e += 256) {
        int r = e >> 7, d = e & 127;
        int n = nb * 32 + r;
        float v = 0.0f;
        if (n < NTOK)
            v = g_qkv[(size_t)(b * NTOK + n) * HID + h * HPER + 2 * KD + d];
        tile[r * 133 + d] = v;
    }
    __syncthreads();
    for (int e = tid; e < 128 * 32; e += 256) {
        int d = e >> 5, r = e & 31;
        int n = nb * 32 + r;
        float f = tile[r * 133 + d];
        __half hv = __float2half(f);
        __half lv = __float2half(f - __half2float(hv));
        size_t o = ((size_t)bh * 128 + d) * 256 + n;
        g_vth[o] = hv;
        g_vtl[o] = lv;
    }
}

// ---------------- tensor-core flash attention (R6-proven) ---------------------
#define SQ_OFF  0
#define SK_OFF  17920
#define SVH_OFF (SK_OFF + 20480)
#define SVL_OFF (SVH_OFF + 67584)
#define ATT_SMEM (SVL_OFF + 67584)

__global__ __launch_bounds__(224, 1) void attn_tc_kernel() {
    extern __shared__ char sm[];
    const uint32_t sb = smem_u32(sm);
    const int tid = threadIdx.x, w = tid >> 5, lane = tid & 31;
    const int h = blockIdx.x, b = blockIdx.y, bh = b * NH + h;

    {
        const uint4* sq = (const uint4*)(g_q  + (size_t)bh * 224 * 32);
        for (int i = tid; i < 896; i += 224) {
            int r = i >> 2, c = i & 3;
            *(uint4*)(sm + SQ_OFF + r * 80 + c * 16) = sq[i];
        }
        const uint4* sk = (const uint4*)(g_kk + (size_t)bh * 256 * 32);
        for (int i = tid; i < 1024; i += 224) {
            int r = i >> 2, c = i & 3;
            *(uint4*)(sm + SK_OFF + r * 80 + c * 16) = sk[i];
        }
        const uint4* vh = (const uint4*)(g_vth + (size_t)bh * 128 * 256);
        const uint4* vl = (const uint4*)(g_vtl + (size_t)bh * 128 * 256);
        for (int i = tid; i < 4096; i += 224) {
            int r = i >> 5, c = i & 31;
            *(uint4*)(sm + SVH_OFF + r * 528 + c * 16) = vh[i];
            *(uint4*)(sm + SVL_OFF + r * 528 + c * 16) = vl[i];
        }
    }
    __syncthreads();

    const int a_row = (lane & 7) + ((lane >> 3) & 1) * 8;
    const int a_kof = ((lane >> 4) & 1) * 8;
    const int b_mat = lane >> 3;
    const int b_row = ((b_mat >> 1) * 8) + (lane & 7);
    const int b_kof = (b_mat & 1) * 8;

    uint32_t qf[2][2][4];
#pragma unroll
    for (int mt = 0; mt < 2; mt++)
#pragma unroll
        for (int kt = 0; kt < 2; kt++)
            ldsm_x4(qf[mt][kt],
                    sb + SQ_OFF + (w * 32 + mt * 16 + a_row) * 80 + (kt * 16 + a_kof) * 2);

    float o[2][16][4];
#pragma unroll
    for (int mt = 0; mt < 2; mt++)
#pragma unroll
        for (int di = 0; di < 16; di++)
#pragma unroll
            for (int j = 0; j < 4; j++) o[mt][di][j] = 0.0f;

    float mcur[2][2] = {{-1e30f, -1e30f}, {-1e30f, -1e30f}};
    float lsum[2][2] = {{0.0f, 0.0f}, {0.0f, 0.0f}};

    const float scale = 0.1767766952966369f;
    const int qr = lane >> 2, qc = (lane & 3) * 2;

    for (int kb = 0; kb < 4; kb++) {
        float s[2][8][4];
#pragma unroll
        for (int mt = 0; mt < 2; mt++)
#pragma unroll
            for (int ni = 0; ni < 8; ni++)
#pragma unroll
                for (int j = 0; j < 4; j++) s[mt][ni][j] = 0.0f;

#pragma unroll
        for (int kt = 0; kt < 2; kt++) {
            uint32_t kf[4][4];
#pragma unroll
            for (int p = 0; p < 4; p++)
                ldsm_x4(kf[p], sb + SK_OFF + (kb * 64 + p * 16 + b_row) * 80
                               + (kt * 16 + b_kof) * 2);
#pragma unroll
            for (int mt = 0; mt < 2; mt++)
#pragma unroll
                for (int ni = 0; ni < 8; ni++)
                    mma_f16(s[mt][ni], qf[mt][kt], &kf[ni >> 1][(ni & 1) * 2]);
        }

#pragma unroll
        for (int mt = 0; mt < 2; mt++)
#pragma unroll
            for (int hf = 0; hf < 2; hf++) {
                int row = w * 32 + mt * 16 + qr + hf * 8;
                int rowc = min(row, NTOK - 1);
                const float* bb = g_bias + (size_t)h * NPAIR + rowc * NTOK;
                int j0 = hf * 2;
#pragma unroll
                for (int ni = 0; ni < 8; ni++) {
                    int key = kb * 64 + ni * 8 + qc;
                    if (key < NTOK) {
                        float2 bv = *(const float2*)(bb + key);
                        s[mt][ni][j0]     = fmaf(s[mt][ni][j0],     scale, bv.x);
                        s[mt][ni][j0 + 1] = fmaf(s[mt][ni][j0 + 1], scale, bv.y);
                    } else {
                        s[mt][ni][j0] = -1e30f;
                        s[mt][ni][j0 + 1] = -1e30f;
                    }
                }
            }

        float alpha[2][2], mnew[2][2];
#pragma unroll
        for (int mt = 0; mt < 2; mt++)
#pragma unroll
            for (int hf = 0; hf < 2; hf++) {
                int j0 = hf * 2;
                float bm = -1e30f;
#pragma unroll
                for (int ni = 0; ni < 8; ni++)
                    bm = fmaxf(bm, fmaxf(s[mt][ni][j0], s[mt][ni][j0 + 1]));
                bm = fmaxf(bm, __shfl_xor_sync(0xffffffffu, bm, 1));
                bm = fmaxf(bm, __shfl_xor_sync(0xffffffffu, bm, 2));
                float mn = fmaxf(mcur[mt][hf], bm);
                alpha[mt][hf] = __expf(mcur[mt][hf] - mn);
                mnew[mt][hf] = mn;
                mcur[mt][hf] = mn;
            }
#pragma unroll
        for (int mt = 0; mt < 2; mt++)
#pragma unroll
            for (int hf = 0; hf < 2; hf++) {
                int j0 = hf * 2;
                float ps = 0.0f;
#pragma unroll
                for (int ni = 0; ni < 8; ni++) {
                    float p0 = __expf(s[mt][ni][j0]     - mnew[mt][hf]);
                    float p1 = __expf(s[mt][ni][j0 + 1] - mnew[mt][hf]);
                    s[mt][ni][j0] = p0; s[mt][ni][j0 + 1] = p1;
                    ps += p0 + p1;
                }
                ps += __shfl_xor_sync(0xffffffffu, ps, 1);
                ps += __shfl_xor_sync(0xffffffffu, ps, 2);
                lsum[mt][hf] = lsum[mt][hf] * alpha[mt][hf] + ps;
                float a = alpha[mt][hf];
#pragma unroll
                for (int di = 0; di < 16; di++) {
                    o[mt][di][j0] *= a;
                    o[mt][di][j0 + 1] *= a;
                }
            }

        uint32_t ph[2][4][4], pl[2][4][4];
#pragma unroll
        for (int mt = 0; mt < 2; mt++)
#pragma unroll
            for (int ks = 0; ks < 4; ks++)
#pragma unroll
                for (int rr = 0; rr < 4; rr++) {
                    int ni = 2 * ks + (rr >> 1);
                    int j  = (rr & 1) * 2;
                    float x = s[mt][ni][j], y = s[mt][ni][j + 1];
                    __half2 hh = __floats2half2_rn(x, y);
                    float rx = x - __low2float(hh), ry = y - __high2float(hh);
                    __half2 hl = __floats2half2_rn(rx, ry);
                    ph[mt][ks][rr] = *reinterpret_cast<uint32_t*>(&hh);
                    pl[mt][ks][rr] = *reinterpret_cast<uint32_t*>(&hl);
                }

#pragma unroll
        for (int ks = 0; ks < 4; ks++)
#pragma unroll
            for (int dp = 0; dp < 8; dp++) {
                uint32_t v4[4];
                ldsm_x4(v4, sb + SVH_OFF + (dp * 16 + b_row) * 528
                            + (kb * 64 + ks * 16 + b_kof) * 2);
#pragma unroll
                for (int mt = 0; mt < 2; mt++) {
                    mma_f16(o[mt][2 * dp],     ph[mt][ks], &v4[0]);
                    mma_f16(o[mt][2 * dp + 1], ph[mt][ks], &v4[2]);
                    mma_f16(o[mt][2 * dp],     pl[mt][ks], &v4[0]);
                    mma_f16(o[mt][2 * dp + 1], pl[mt][ks], &v4[2]);
                }
                ldsm_x4(v4, sb + SVL_OFF + (dp * 16 + b_row) * 528
                            + (kb * 64 + ks * 16 + b_kof) * 2);
#pragma unroll
                for (int mt = 0; mt < 2; mt++) {
                    mma_f16(o[mt][2 * dp],     ph[mt][ks], &v4[0]);
                    mma_f16(o[mt][2 * dp + 1], ph[mt][ks], &v4[2]);
                }
            }
    }

#pragma unroll
    for (int mt = 0; mt < 2; mt++)
#pragma unroll
        for (int hf = 0; hf < 2; hf++) {
            int row = w * 32 + mt * 16 + qr + hf * 8;
            if (row >= NTOK) continue;
            float inv = 1.0f / lsum[mt][hf];
            int j0 = hf * 2;
            size_t base = (size_t)(b * NTOK + row) * (NH * VD) + h * VD;
#pragma unroll
            for (int di = 0; di < 16; di++) {
                int d = di * 8 + qc;
                float v0 = o[mt][di][j0] * inv;
                float v1 = o[mt][di][j0 + 1] * inv;
                *(__half2*)(g_aoh + base + d) = __floats2half2_rn(v0, v1);
            }
        }
}

// ---------------- launch ------------------------------------------------------
extern "C" void kernel_launch(void* const* d_in, const int* in_sizes, int n_in,
                              void* d_out, int out_size) {
    const float* x     = (const float*)d_in[0];
    const float* Wqkv  = (const float*)d_in[1];
    const float* bqkv  = (const float*)d_in[2];
    const float* Wproj = (const float*)d_in[3];
    const float* bproj = (const float*)d_in[4];
    const float* ab    = (const float*)d_in[5];
    const int*   idxs  = (const int*)  d_in[6];
    float* out = (float*)d_out;

    int n_off = in_sizes[5] / NH;

    void *p_qkv, *p_xh, *p_wqh, *p_wph, *p_aoh;
    cudaGetSymbolAddress(&p_qkv, g_qkv);
    cudaGetSymbolAddress(&p_xh, g_xh);
    cudaGetSymbolAddress(&p_wqh, g_wqh);
    cudaGetSymbolAddress(&p_wph, g_wph);
    cudaGetSymbolAddress(&p_aoh, g_aoh);

    cudaFuncSetAttribute(gemm_mma_kernel,
                         cudaFuncAttributeMaxDynamicSharedMemorySize, GEMM_SMEM);
    cudaFuncSetAttribute(attn_tc_kernel,
                         cudaFuncAttributeMaxDynamicSharedMemorySize, ATT_SMEM);

    bias_fill_kernel<<<(NPAIR + 255) / 256, 256>>>(idxs, ab, n_off);
    {
        int n4 = MROWS * DIM / 4;
        split_hi_kernel<<<(n4 + 255) / 256, 256>>>(x, (__half*)p_xh, n4);
    }
    {
        int n4 = HID * DIM / 4;
        split_hi_kernel<<<(n4 + 255) / 256, 256>>>(Wqkv, (__half*)p_wqh, n4);
    }
    {
        int n4 = DIM * NH * VD / 4;
        split_hi_kernel<<<(n4 + 255) / 256, 256>>>(Wproj, (__half*)p_wph, n4);
    }

    // QKV gemm -> g_qkv (fp32): K=384 -> 6 chunks of 64
    gemm_mma_kernel<<<dim3(HID / 128, MROWS / 128), 256, GEMM_SMEM>>>(
        (const __half*)p_xh, (const __half*)p_wqh,
        bqkv, (float*)p_qkv, HID, DIM, DIM / 64);

    // repack to fp16 attention operands
    {
        int tot = NBH * NTOK * 16;
        qk_repack_kernel<<<(tot + 255) / 256, 256>>>();
    }
    v_repack_kernel<<<dim3(7, NBH), 256>>>();

    // tensor-core flash attention -> g_aoh
    attn_tc_kernel<<<dim3(NH, BSZ), 224, ATT_SMEM>>>();

    // proj gemm -> out: K=1024 -> 16 chunks of 64
    gemm_mma_kernel<<<dim3(DIM / 128, MROWS / 128), 256, GEMM_SMEM>>>(
        (const __half*)p_aoh, (const __half*)p_wph,
        bproj, out, DIM, NH * VD, (NH * VD) / 64);
}

// round 17
// speedup vs baseline: 1.4448x; 1.0869x over previous
#include <cuda_runtime.h>
#include <cuda_bf16.h>
#include <cuda_fp16.h>
#include <cstdint>

#define BSZ  256
#define NTOK 196
#define DIM  384
#define NH   8
#define KD   32
#define VD   128
#define HPER 192
#define HID  1536
#define NPAIR 38416
#define MROWS (BSZ*NTOK)   // 50176
#define NBH   (BSZ*NH)     // 2048

// ---------------- scratch (static device globals; zero-initialized) -----------
__device__ float  g_qkv [(size_t)MROWS * HID];
__device__ float  g_bias[(size_t)NH * NPAIR];
__device__ __half g_xh  [(size_t)MROWS * DIM];
__device__ __half g_wqh [(size_t)HID * DIM];
__device__ __half g_wph [(size_t)DIM * NH * VD];
__device__ __half g_aoh [(size_t)MROWS * NH * VD];
// fp16 attention operands (pads stay zero: never written)
__device__ __half g_q   [(size_t)NBH * 224 * 32];
__device__ __half g_kk  [(size_t)NBH * 256 * 32];
__device__ __half g_vth [(size_t)NBH * 128 * 256];   // V^T hi

// ---------------- PTX helpers -------------------------------------------------
__device__ __forceinline__ uint32_t smem_u32(const void* p) {
    uint32_t a;
    asm("{ .reg .u64 t; cvta.to.shared.u64 t, %1; cvt.u32.u64 %0, t; }"
        : "=r"(a) : "l"(p));
    return a;
}
__device__ __forceinline__ void ldsm_x4(uint32_t* r, uint32_t addr) {
    asm volatile("ldmatrix.sync.aligned.m8n8.x4.shared.b16 {%0,%1,%2,%3}, [%4];"
        : "=r"(r[0]), "=r"(r[1]), "=r"(r[2]), "=r"(r[3]) : "r"(addr));
}
__device__ __forceinline__ void mma_f16(float* c, const uint32_t* a, const uint32_t* b) {
    asm volatile(
        "mma.sync.aligned.m16n8k16.row.col.f32.f16.f16.f32 "
        "{%0,%1,%2,%3}, {%4,%5,%6,%7}, {%8,%9}, {%0,%1,%2,%3};"
        : "+f"(c[0]), "+f"(c[1]), "+f"(c[2]), "+f"(c[3])
        : "r"(a[0]), "r"(a[1]), "r"(a[2]), "r"(a[3]), "r"(b[0]), "r"(b[1]));
}

// ---------------- bias table precompute --------------------------------------
__global__ void bias_fill_kernel(const int* __restrict__ idx_raw,
                                 const float* __restrict__ ab, int n_off) {
    int i = blockIdx.x * blockDim.x + threadIdx.x;
    if (i >= NPAIR) return;
    bool is64 = (idx_raw[1] == 0);
    int idx = is64 ? idx_raw[2 * i] : idx_raw[i];
#pragma unroll
    for (int h = 0; h < NH; h++)
        g_bias[(size_t)h * NPAIR + i] = ab[h * n_off + idx];
}

// ---------------- fp32 -> fp16 convert (hi only) -------------------------------
__global__ void split_hi_kernel(const float* __restrict__ src,
                                __half* __restrict__ hi, int n4) {
    int i = blockIdx.x * blockDim.x + threadIdx.x;
    if (i >= n4) return;
    float4 v = ((const float4*)src)[i];
    ((__half2*)hi)[2 * i]     = __floats2half2_rn(v.x, v.y);
    ((__half2*)hi)[2 * i + 1] = __floats2half2_rn(v.z, v.w);
}

// ---------------- fp16 1-pass GEMM, K-chunk 128, 2 CTAs/SM --------------------
// C = Ah @ Bh^T + bias, fp32 accum. Chunk 128 halves per-chunk overhead events
// again; (256,2) co-residency hides the rest. Row pad 136 (272 B; 272%128=16
// -> 8 ldsm rows hit 8 distinct bank groups, conflict-free).
#define TPAD3 136
#define TILE_B3 (128 * TPAD3 * 2)    // 34816 B
#define T_AH 0
#define T_BH (TILE_B3)
#define GEMM_SMEM (2 * TILE_B3)      // 69632 B

__global__ __launch_bounds__(256, 2) void gemm_mma_kernel(
    const __half* __restrict__ Ah, const __half* __restrict__ Bh,
    const float* __restrict__ bias, float* __restrict__ C,
    int Ndim, int Kdim, int nchunk)
{
    extern __shared__ char smem[];
    const uint32_t sb = smem_u32(smem);
    const int tid = threadIdx.x;
    const int wid = tid >> 5, lane = tid & 31;
    const int wm = wid & 1, wn = wid >> 1;
    const int bm = blockIdx.y, bn = blockIdx.x;

    const __half* srcs[2] = {Ah + (size_t)bm * 128 * Kdim,
                             Bh + (size_t)bn * 128 * Kdim};
    const int toffs[2] = {T_AH, T_BH};

    float acc[4][4][4];
#pragma unroll
    for (int i = 0; i < 4; i++)
#pragma unroll
        for (int j = 0; j < 4; j++)
#pragma unroll
            for (int r = 0; r < 4; r++) acc[i][j][r] = 0.0f;

    const int a_row = (lane & 7) + ((lane >> 3) & 1) * 8;
    const int a_kof = ((lane >> 4) & 1) * 8;
    const int b_mat = lane >> 3;
    const int b_row = ((b_mat >> 1) * 8) + (lane & 7);
    const int b_kof = (b_mat & 1) * 8;

    for (int c = 0; c < nchunk; c++) {
        const int k0 = c * 128;
        if (c > 0) __syncthreads();
        // each tile: 128 rows x 128 fp16 = 2048 uint4; 2 tiles, 256 threads
#pragma unroll
        for (int t = 0; t < 2; t++) {
            const __half* s = srcs[t];
#pragma unroll
            for (int u = tid; u < 2048; u += 256) {
                int row = u >> 4, seg = u & 15;
                uint4 v = *(const uint4*)(s + (size_t)row * Kdim + k0 + seg * 8);
                *(uint4*)(smem + toffs[t] + row * (TPAD3 * 2) + seg * 16) = v;
            }
        }
        __syncthreads();

#pragma unroll
        for (int ks = 0; ks < 8; ks++) {
            const int kk = ks * 16;
            uint32_t ah[4][4], bh[2][4];
#pragma unroll
            for (int mi = 0; mi < 4; mi++) {
                int row = wm * 64 + mi * 16 + a_row;
                ldsm_x4(ah[mi], sb + T_AH + row * (TPAD3 * 2) + (kk + a_kof) * 2);
            }
#pragma unroll
            for (int p = 0; p < 2; p++) {
                int nrow = wn * 32 + p * 16 + b_row;
                ldsm_x4(bh[p], sb + T_BH + nrow * (TPAD3 * 2) + (kk + b_kof) * 2);
            }
#pragma unroll
            for (int mi = 0; mi < 4; mi++)
#pragma unroll
                for (int ni = 0; ni < 4; ni++)
                    mma_f16(acc[mi][ni], ah[mi], &bh[ni >> 1][(ni & 1) * 2]);
        }
    }

    const int m0 = bm * 128 + wm * 64;
    const int n0 = bn * 128 + wn * 32;
    const int tr = lane >> 2, tc = (lane & 3) * 2;
#pragma unroll
    for (int mi = 0; mi < 4; mi++)
#pragma unroll
        for (int ni = 0; ni < 4; ni++) {
            int row = m0 + mi * 16 + tr;
            int col = n0 + ni * 8 + tc;
            float b0 = __ldg(bias + col), b1 = __ldg(bias + col + 1);
            float2 v0 = {acc[mi][ni][0] + b0, acc[mi][ni][1] + b1};
            float2 v1 = {acc[mi][ni][2] + b0, acc[mi][ni][3] + b1};
            *(float2*)(C + (size_t)row * Ndim + col) = v0;
            *(float2*)(C + (size_t)(row + 8) * Ndim + col) = v1;
        }
}

// ---------------- QKV fp32 -> fp16 Q/K repack ---------------------------------
__global__ void qk_repack_kernel() {
    int i = blockIdx.x * blockDim.x + threadIdx.x;
    if (i >= NBH * NTOK * 16) return;
    int g  = i & 15;
    int bn = i >> 4;
    int bh = bn / NTOK, n = bn - bh * NTOK;
    int b = bh >> 3, h = bh & 7;
    const float* src = g_qkv + (size_t)(b * NTOK + n) * HID + h * HPER + g * 4;
    float4 v = *(const float4*)src;
    __half tmp[4];
    tmp[0] = __float2half(v.x); tmp[1] = __float2half(v.y);
    tmp[2] = __float2half(v.z); tmp[3] = __float2half(v.w);
    __half* dst = (g < 8)
        ? (g_q  + ((size_t)bh * 224 + n) * 32 + g * 4)
        : (g_kk + ((size_t)bh * 256 + n) * 32 + (g - 8) * 4);
    *(uint2*)dst = *(uint2*)tmp;
}

// ---------------- V transpose (fp16 hi only) ----------------------------------
__global__ __launch_bounds__(256) void v_repack_kernel() {
    __shared__ float tile[32 * 133];
    const int nb = blockIdx.x, bh = blockIdx.y;
    const int b = bh >> 3, h = bh & 7;
    const int tid = threadIdx.x;

    for (int e = tid; e < 32 * 128; e += 256) {
        int r = e >> 7, d = e & 127;
        int n = nb * 32 + r;
        float v = 0.0f;
        if (n < NTOK)
            v = g_qkv[(size_t)(b * NTOK + n) * HID + h * HPER + 2 * KD + d];
        tile[r * 133 + d] = v;
    }
    __syncthreads();
    for (int e = tid; e < 128 * 32; e += 256) {
        int d = e >> 5, r = e & 31;
        int n = nb * 32 + r;
        g_vth[((size_t)bh * 128 + d) * 256 + n] = __float2half(tile[r * 133 + d]);
    }
}

// ---------------- tensor-core flash attention (PV 2-pass: PhVh + PlVh) --------
#define SQ_OFF  0
#define SK_OFF  17920
#define SVH_OFF (SK_OFF + 20480)
#define ATT_SMEM (SVH_OFF + 67584)   // 105984

__global__ __launch_bounds__(224, 1) void attn_tc_kernel() {
    extern __shared__ char sm[];
    const uint32_t sb = smem_u32(sm);
    const int tid = threadIdx.x, w = tid >> 5, lane = tid & 31;
    const int h = blockIdx.x, b = blockIdx.y, bh = b * NH + h;

    {
        const uint4* sq = (const uint4*)(g_q  + (size_t)bh * 224 * 32);
        for (int i = tid; i < 896; i += 224) {
            int r = i >> 2, c = i & 3;
            *(uint4*)(sm + SQ_OFF + r * 80 + c * 16) = sq[i];
        }
        const uint4* sk = (const uint4*)(g_kk + (size_t)bh * 256 * 32);
        for (int i = tid; i < 1024; i += 224) {
            int r = i >> 2, c = i & 3;
            *(uint4*)(sm + SK_OFF + r * 80 + c * 16) = sk[i];
        }
        const uint4* vh = (const uint4*)(g_vth + (size_t)bh * 128 * 256);
        for (int i = tid; i < 4096; i += 224) {
            int r = i >> 5, c = i & 31;
            *(uint4*)(sm + SVH_OFF + r * 528 + c * 16) = vh[i];
        }
    }
    __syncthreads();

    const int a_row = (lane & 7) + ((lane >> 3) & 1) * 8;
    const int a_kof = ((lane >> 4) & 1) * 8;
    const int b_mat = lane >> 3;
    const int b_row = ((b_mat >> 1) * 8) + (lane & 7);
    const int b_kof = (b_mat & 1) * 8;

    uint32_t qf[2][2][4];
#pragma unroll
    for (int mt = 0; mt < 2; mt++)
#pragma unroll
        for (int kt = 0; kt < 2; kt++)
            ldsm_x4(qf[mt][kt],
                    sb + SQ_OFF + (w * 32 + mt * 16 + a_row) * 80 + (kt * 16 + a_kof) * 2);

    float o[2][16][4];
#pragma unroll
    for (int mt = 0; mt < 2; mt++)
#pragma unroll
        for (int di = 0; di < 16; di++)
#pragma unroll
            for (int j = 0; j < 4; j++) o[mt][di][j] = 0.0f;

    float mcur[2][2] = {{-1e30f, -1e30f}, {-1e30f, -1e30f}};
    float lsum[2][2] = {{0.0f, 0.0f}, {0.0f, 0.0f}};

    const float scale = 0.1767766952966369f;
    const int qr = lane >> 2, qc = (lane & 3) * 2;

    for (int kb = 0; kb < 4; kb++) {
        float s[2][8][4];
#pragma unroll
        for (int mt = 0; mt < 2; mt++)
#pragma unroll
            for (int ni = 0; ni < 8; ni++)
#pragma unroll
                for (int j = 0; j < 4; j++) s[mt][ni][j] = 0.0f;

#pragma unroll
        for (int kt = 0; kt < 2; kt++) {
            uint32_t kf[4][4];
#pragma unroll
            for (int p = 0; p < 4; p++)
                ldsm_x4(kf[p], sb + SK_OFF + (kb * 64 + p * 16 + b_row) * 80
                               + (kt * 16 + b_kof) * 2);
#pragma unroll
            for (int mt = 0; mt < 2; mt++)
#pragma unroll
                for (int ni = 0; ni < 8; ni++)
                    mma_f16(s[mt][ni], qf[mt][kt], &kf[ni >> 1][(ni & 1) * 2]);
        }

#pragma unroll
        for (int mt = 0; mt < 2; mt++)
#pragma unroll
            for (int hf = 0; hf < 2; hf++) {
                int row = w * 32 + mt * 16 + qr + hf * 8;
                int rowc = min(row, NTOK - 1);
                const float* bb = g_bias + (size_t)h * NPAIR + rowc * NTOK;
                int j0 = hf * 2;
#pragma unroll
                for (int ni = 0; ni < 8; ni++) {
                    int key = kb * 64 + ni * 8 + qc;
                    if (key < NTOK) {
                        float2 bv = *(const float2*)(bb + key);
                        s[mt][ni][j0]     = fmaf(s[mt][ni][j0],     scale, bv.x);
                        s[mt][ni][j0 + 1] = fmaf(s[mt][ni][j0 + 1], scale, bv.y);
                    } else {
                        s[mt][ni][j0] = -1e30f;
                        s[mt][ni][j0 + 1] = -1e30f;
                    }
                }
            }

        float alpha[2][2], mnew[2][2];
#pragma unroll
        for (int mt = 0; mt < 2; mt++)
#pragma unroll
            for (int hf = 0; hf < 2; hf++) {
                int j0 = hf * 2;
                float bm = -1e30f;
#pragma unroll
                for (int ni = 0; ni < 8; ni++)
                    bm = fmaxf(bm, fmaxf(s[mt][ni][j0], s[mt][ni][j0 + 1]));
                bm = fmaxf(bm, __shfl_xor_sync(0xffffffffu, bm, 1));
                bm = fmaxf(bm, __shfl_xor_sync(0xffffffffu, bm, 2));
                float mn = fmaxf(mcur[mt][hf], bm);
                alpha[mt][hf] = __expf(mcur[mt][hf] - mn);
                mnew[mt][hf] = mn;
                mcur[mt][hf] = mn;
            }
#pragma unroll
        for (int mt = 0; mt < 2; mt++)
#pragma unroll
            for (int hf = 0; hf < 2; hf++) {
                int j0 = hf * 2;
                float ps = 0.0f;
#pragma unroll
                for (int ni = 0; ni < 8; ni++) {
                    float p0 = __expf(s[mt][ni][j0]     - mnew[mt][hf]);
                    float p1 = __expf(s[mt][ni][j0 + 1] - mnew[mt][hf]);
                    s[mt][ni][j0] = p0; s[mt][ni][j0 + 1] = p1;
                    ps += p0 + p1;
                }
                ps += __shfl_xor_sync(0xffffffffu, ps, 1);
                ps += __shfl_xor_sync(0xffffffffu, ps, 2);
                lsum[mt][hf] = lsum[mt][hf] * alpha[mt][hf] + ps;
                float a = alpha[mt][hf];
#pragma unroll
                for (int di = 0; di < 16; di++) {
                    o[mt][di][j0] *= a;
                    o[mt][di][j0 + 1] *= a;
                }
            }

        uint32_t ph[2][4][4], pl[2][4][4];
#pragma unroll
        for (int mt = 0; mt < 2; mt++)
#pragma unroll
            for (int ks = 0; ks < 4; ks++)
#pragma unroll
                for (int rr = 0; rr < 4; rr++) {
                    int ni = 2 * ks + (rr >> 1);
                    int j  = (rr & 1) * 2;
                    float x = s[mt][ni][j], y = s[mt][ni][j + 1];
                    __half2 hh = __floats2half2_rn(x, y);
                    float rx = x - __low2float(hh), ry = y - __high2float(hh);
                    __half2 hl = __floats2half2_rn(rx, ry);
                    ph[mt][ks][rr] = *reinterpret_cast<uint32_t*>(&hh);
                    pl[mt][ks][rr] = *reinterpret_cast<uint32_t*>(&hl);
                }

        // PV 2-pass: PhVh + PlVh (V-lo term dropped, ~1.5e-4 RMS)
#pragma unroll
        for (int ks = 0; ks < 4; ks++)
#pragma unroll
            for (int dp = 0; dp < 8; dp++) {
                uint32_t v4[4];
                ldsm_x4(v4, sb + SVH_OFF + (dp * 16 + b_row) * 528
                            + (kb * 64 + ks * 16 + b_kof) * 2);
#pragma unroll
                for (int mt = 0; mt < 2; mt++) {
                    mma_f16(o[mt][2 * dp],     ph[mt][ks], &v4[0]);
                    mma_f16(o[mt][2 * dp + 1], ph[mt][ks], &v4[2]);
                    mma_f16(o[mt][2 * dp],     pl[mt][ks], &v4[0]);
                    mma_f16(o[mt][2 * dp + 1], pl[mt][ks], &v4[2]);
                }
            }
    }

#pragma unroll
    for (int mt = 0; mt < 2; mt++)
#pragma unroll
        for (int hf = 0; hf < 2; hf++) {
            int row = w * 32 + mt * 16 + qr + hf * 8;
            if (row >= NTOK) continue;
            float inv = 1.0f / lsum[mt][hf];
            int j0 = hf * 2;
            size_t base = (size_t)(b * NTOK + row) * (NH * VD) + h * VD;
#pragma unroll
            for (int di = 0; di < 16; di++) {
                int d = di * 8 + qc;
                float v0 = o[mt][di][j0] * inv;
                float v1 = o[mt][di][j0 + 1] * inv;
                *(__half2*)(g_aoh + base + d) = __floats2half2_rn(v0, v1);
            }
        }
}

// ---------------- launch ------------------------------------------------------
extern "C" void kernel_launch(void* const* d_in, const int* in_sizes, int n_in,
                              void* d_out, int out_size) {
    const float* x     = (const float*)d_in[0];
    const float* Wqkv  = (const float*)d_in[1];
    const float* bqkv  = (const float*)d_in[2];
    const float* Wproj = (const float*)d_in[3];
    const float* bproj = (const float*)d_in[4];
    const float* ab    = (const float*)d_in[5];
    const int*   idxs  = (const int*)  d_in[6];
    float* out = (float*)d_out;

    int n_off = in_sizes[5] / NH;

    void *p_qkv, *p_xh, *p_wqh, *p_wph, *p_aoh;
    cudaGetSymbolAddress(&p_qkv, g_qkv);
    cudaGetSymbolAddress(&p_xh, g_xh);
    cudaGetSymbolAddress(&p_wqh, g_wqh);
    cudaGetSymbolAddress(&p_wph, g_wph);
    cudaGetSymbolAddress(&p_aoh, g_aoh);

    cudaFuncSetAttribute(gemm_mma_kernel,
                         cudaFuncAttributeMaxDynamicSharedMemorySize, GEMM_SMEM);
    cudaFuncSetAttribute(attn_tc_kernel,
                         cudaFuncAttributeMaxDynamicSharedMemorySize, ATT_SMEM);

    bias_fill_kernel<<<(NPAIR + 255) / 256, 256>>>(idxs, ab, n_off);
    {
        int n4 = MROWS * DIM / 4;
        split_hi_kernel<<<(n4 + 255) / 256, 256>>>(x, (__half*)p_xh, n4);
    }
    {
        int n4 = HID * DIM / 4;
        split_hi_kernel<<<(n4 + 255) / 256, 256>>>(Wqkv, (__half*)p_wqh, n4);
    }
    {
        int n4 = DIM * NH * VD / 4;
        split_hi_kernel<<<(n4 + 255) / 256, 256>>>(Wproj, (__half*)p_wph, n4);
    }

    // QKV gemm -> g_qkv (fp32): K=384 -> 3 chunks of 128
    gemm_mma_kernel<<<dim3(HID / 128, MROWS / 128), 256, GEMM_SMEM>>>(
        (const __half*)p_xh, (const __half*)p_wqh,
        bqkv, (float*)p_qkv, HID, DIM, DIM / 128);

    // repack to fp16 attention operands
    {
        int tot = NBH * NTOK * 16;
        qk_repack_kernel<<<(tot + 255) / 256, 256>>>();
    }
    v_repack_kernel<<<dim3(7, NBH), 256>>>();

    // tensor-core flash attention -> g_aoh
    attn_tc_kernel<<<dim3(NH, BSZ), 224, ATT_SMEM>>>();

    // proj gemm -> out: K=1024 -> 8 chunks of 128
    gemm_mma_kernel<<<dim3(DIM / 128, MROWS / 128), 256, GEMM_SMEM>>>(
        (const __half*)p_aoh, (const __half*)p_wph,
        bproj, out, DIM, NH * VD, (NH * VD) / 128);
}